// round 13
// baseline (speedup 1.0000x reference)
#include <cuda_runtime.h>
#include <float.h>

// ---------------------------------------------------------------------------
// FeatPropagation via uniform-grid EXACT k=3 NN + inverse-distance interp.
//
// R13: WARP-PER-QUERY scan. R12's profile (knn_cell 124us, issue 26%, mem
// <9%, occ 40%) exposed the real binder: one partially-filled warp per cell
// serially scanning ~700 candidates while 3 warps idle. Now each warp owns
// one query and its 32 lanes stride the SMEM-staged candidate list (lane-
// local top-3 over disjoint subsets + exact warp tree-merge). Unroll-4 keeps
// 4 LDS.128 in flight per lane. Queries failing the r=1 stop bound (and
// cells overflowing the SMEM stage) go to g_far -> knn_far (R10's verified
// exclusive-shell warp-per-query walk).
//
// Ranking stays BIT-EXACT vs the JAX reference (GEMM-form d2 with explicit
// rounding intrinsics); (d2, index) lexicographic insert == top_k
// lowest-index tie-break, independent of partition/scatter/list order.
// ---------------------------------------------------------------------------

#define G      16
#define G3     (G * G * G)
#define GLO    (-4.0f)
#define HV     0.5f
#define INVH   2.0f
#define MAXB   8
#define MARGIN 2e-4f

__device__ int    g_cnt[MAXB * G3];
__device__ int    g_start[MAXB * (G3 + 1)];
__device__ int    g_cur[MAXB * G3];
__device__ float4 g_pts[1 << 15];
__device__ int    g_pid[1 << 15];
__device__ int    g_qcnt[MAXB * G3];
__device__ int    g_qstart[MAXB * (G3 + 1)];
__device__ int    g_qcur[MAXB * G3];
__device__ float4 g_qpts[1 << 17];
__device__ int    g_qid[1 << 17];
__device__ int    g_nfar;
__device__ int    g_far[1 << 17];

#define CAPQ (3 * (1 << 17))
__device__ int   g_idx[CAPQ];          // by ORIGINAL query id
__device__ float g_w[CAPQ];

__device__ __forceinline__ int cell1(float v) {
    int c = (int)floorf((v - GLO) * INVH);
    return min(max(c, 0), G - 1);
}

__global__ void count_all(const float* __restrict__ xyz,
                          const float* __restrict__ qxyz,
                          int N, int Ntot, int M, int Mtot) {
    int i = blockIdx.x * blockDim.x + threadIdx.x;
    if (i < Ntot) {
        int b = i / N;
        float x = xyz[3 * i], y = xyz[3 * i + 1], z = xyz[3 * i + 2];
        atomicAdd(g_cnt + b * G3 + (cell1(z) * G + cell1(y)) * G + cell1(x), 1);
    } else if (i < Ntot + Mtot) {
        int j = i - Ntot;
        int b = j / M;
        float x = qxyz[3 * j], y = qxyz[3 * j + 1], z = qxyz[3 * j + 2];
        atomicAdd(g_qcnt + b * G3 + (cell1(z) * G + cell1(y)) * G + cell1(x), 1);
    }
}

__global__ void __launch_bounds__(1024) scan_kernel() {
    const int b = blockIdx.x;
    int* cnt   = (blockIdx.y ? g_qcnt   : g_cnt)   + b * G3;
    int* start = (blockIdx.y ? g_qstart : g_start) + b * (G3 + 1);
    int* cur   = (blockIdx.y ? g_qcur   : g_cur)   + b * G3;

    const int tid = threadIdx.x;
    __shared__ int sm[1024];

    const int lo = tid * 4;
    int c0 = cnt[lo], c1 = cnt[lo + 1], c2 = cnt[lo + 2], c3 = cnt[lo + 3];
    const int sum = c0 + c1 + c2 + c3;
    sm[tid] = sum;
    __syncthreads();
    for (int off = 1; off < 1024; off <<= 1) {
        int v = (tid >= off) ? sm[tid - off] : 0;
        __syncthreads();
        sm[tid] += v;
        __syncthreads();
    }
    int run = sm[tid] - sum;
    start[lo]     = run;  cur[lo]     = run;  run += c0;
    start[lo + 1] = run;  cur[lo + 1] = run;  run += c1;
    start[lo + 2] = run;  cur[lo + 2] = run;  run += c2;
    start[lo + 3] = run;  cur[lo + 3] = run;
    if (tid == 1023) start[G3] = sm[1023];
}

__global__ void scatter_all(const float* __restrict__ xyz,
                            const float* __restrict__ qxyz,
                            int N, int Ntot, int M, int Mtot) {
    int i = blockIdx.x * blockDim.x + threadIdx.x;
    if (i < Ntot) {
        int b = i / N;
        float x = xyz[3 * i], y = xyz[3 * i + 1], z = xyz[3 * i + 2];
        int c = (cell1(z) * G + cell1(y)) * G + cell1(x);
        int pos = atomicAdd(g_cur + b * G3 + c, 1);
        float s2 = __fadd_rn(__fadd_rn(__fmul_rn(x, x), __fmul_rn(y, y)),
                             __fmul_rn(z, z));
        g_pts[b * N + pos] = make_float4(x, y, z, s2);
        g_pid[b * N + pos] = i;
    } else if (i < Ntot + Mtot) {
        int j = i - Ntot;
        int b = j / M;
        float x = qxyz[3 * j], y = qxyz[3 * j + 1], z = qxyz[3 * j + 2];
        int c = (cell1(z) * G + cell1(y)) * G + cell1(x);
        int pos = atomicAdd(g_qcur + b * G3 + c, 1);
        float s2 = __fadd_rn(__fadd_rn(__fmul_rn(x, x), __fmul_rn(y, y)),
                             __fmul_rn(z, z));
        g_qpts[b * M + pos] = make_float4(x, y, z, s2);
        g_qid [b * M + pos] = j;
    }
}

__global__ void zero_tail(int cells) {
    int i = blockIdx.x * blockDim.x + threadIdx.x;
    if (i < cells) { g_cnt[i] = 0; g_qcnt[i] = 0; }
    if (i == 0) g_nfar = 0;
}

// ---------------------------------------------------------------------------
// knn_cell: block per (cell,batch) stages the 3x3x3 box; WARP per query,
// lanes stride candidates; exact warp merge; failures -> g_far.
// ---------------------------------------------------------------------------
#define KNN_T  128
#define NW     (KNN_T / 32)
#define CAP_C  1536

__global__ void __launch_bounds__(KNN_T)
knn_cell(int N, int M)
{
    const int b  = blockIdx.y;
    const int c  = blockIdx.x;
    const int bs = b * (G3 + 1);
    const int qs = g_qstart[bs + c];
    const int qe = g_qstart[bs + c + 1];
    if (qs == qe) return;

    const int cz = c / (G * G);
    const int cy = (c / G) % G;
    const int cx = c % G;

    const int pbase = b * N;
    const int qbase = b * M;
    const int tid   = threadIdx.x;
    const int lane  = tid & 31;
    const int warp  = tid >> 5;

    __shared__ int    rowS[9], rowE[9];
    __shared__ float4 spts[CAP_C];
    __shared__ int    sid[CAP_C];

    if (tid < 9) {
        const int dz = tid / 3 - 1, dy = tid % 3 - 1;
        const int z = cz + dz, y = cy + dy;
        int s = 0, e = 0;
        if (z >= 0 && z < G && y >= 0 && y < G) {
            const int xlo = max(cx - 1, 0), xhi = min(cx + 1, G - 1);
            const int row = (z * G + y) * G;
            s = g_start[bs + row + xlo];
            e = g_start[bs + row + xhi + 1];
        }
        rowS[tid] = s; rowE[tid] = e;
    }
    __syncthreads();

    int total = 0;
    #pragma unroll
    for (int r = 0; r < 9; r++) total += rowE[r] - rowS[r];

    if (total > CAP_C) {               // extreme-density guard: punt the cell
        for (int i = qs + tid; i < qe; i += KNN_T)
            g_far[atomicAdd(&g_nfar, 1)] = qbase + i;
        return;
    }

    // cooperative fill (block-uniform control flow)
    int base = 0;
    #pragma unroll
    for (int r = 0; r < 9; r++) {
        const int s = rowS[r], len = rowE[r] - s;
        for (int i = tid; i < len; i += KNN_T) {
            spts[base + i] = g_pts[pbase + s + i];
            sid [base + i] = g_pid[pbase + s + i];
        }
        base += len;
    }
    __syncthreads();

    // warp-per-query scan: lanes stride the candidate list
    for (int qi = qs + warp; qi < qe; qi += NW) {
        const float4 Q   = g_qpts[qbase + qi];
        const int    qid = g_qid[qbase + qi];
        const float qx = Q.x, qy = Q.y, qz = Q.z, q2 = Q.w;

        float d0 = 1e30f, d1 = 1e30f, d2v = 1e30f;
        int   i0 = -1,    i1 = -1,    i2 = -1;

        auto ins = [&](float dd, int id) {
            if (dd < d2v || (dd == d2v && id < i2)) {
                if (dd < d1 || (dd == d1 && id < i1)) {
                    d2v = d1; i2 = i1;
                    if (dd < d0 || (dd == d0 && id < i0)) {
                        d1 = d0; i1 = i0; d0 = dd; i0 = id;
                    } else { d1 = dd; i1 = id; }
                } else { d2v = dd; i2 = id; }
            }
        };
        auto dist2 = [&](const float4& P) -> float {
            const float cross = __fmaf_rn(qz, P.z,
                                  __fmaf_rn(qy, P.y, __fmul_rn(qx, P.x)));
            return __fmaf_rn(-2.0f, cross, __fadd_rn(q2, P.w));
        };

        int j = lane;
        for (; j + 96 < total; j += 128) {       // 4 LDS.128 in flight
            const float4 p0 = spts[j];
            const float4 p1 = spts[j + 32];
            const float4 p2 = spts[j + 64];
            const float4 p3 = spts[j + 96];
            const float dd0 = dist2(p0);
            const float dd1 = dist2(p1);
            const float dd2 = dist2(p2);
            const float dd3 = dist2(p3);
            const float gm  = fminf(fminf(dd0, dd1), fminf(dd2, dd3));
            if (gm <= d2v) {                     // '<=' keeps tie-break exact
                ins(dd0, sid[j]);
                ins(dd1, sid[j + 32]);
                ins(dd2, sid[j + 64]);
                ins(dd3, sid[j + 96]);
            }
        }
        for (; j < total; j += 32)
            ins(dist2(spts[j]), sid[j]);

        // exact warp tree-merge (disjoint partials -> no duplicates)
        float m0 = d0, m1 = d1, m2 = d2v;
        int   j0 = i0, j1 = i1, j2 = i2;
        auto insM = [&](float dd, int id) {
            if (dd < m2 || (dd == m2 && id < j2)) {
                if (dd < m1 || (dd == m1 && id < j1)) {
                    m2 = m1; j2 = j1;
                    if (dd < m0 || (dd == m0 && id < j0)) {
                        m1 = m0; j1 = j0; m0 = dd; j0 = id;
                    } else { m1 = dd; j1 = id; }
                } else { m2 = dd; j2 = id; }
            }
        };
        for (int off = 16; off; off >>= 1) {
            const float b0 = __shfl_down_sync(0xFFFFFFFFu, m0, off);
            const float b1 = __shfl_down_sync(0xFFFFFFFFu, m1, off);
            const float b2 = __shfl_down_sync(0xFFFFFFFFu, m2, off);
            const int   c0 = __shfl_down_sync(0xFFFFFFFFu, j0, off);
            const int   c1 = __shfl_down_sync(0xFFFFFFFFu, j1, off);
            const int   c2 = __shfl_down_sync(0xFFFFFFFFu, j2, off);
            if (lane < off) { insM(b0, c0); insM(b1, c1); insM(b2, c2); }
        }

        if (lane == 0) {
            // stop check on the query's own r=1 box
            bool done = false;
            const float fxl = (cx - 1 <= 0)     ? 1e30f : qx - (GLO + (cx - 1) * HV);
            const float fxh = (cx + 1 >= G - 1) ? 1e30f : (GLO + (cx + 2) * HV) - qx;
            const float fyl = (cy - 1 <= 0)     ? 1e30f : qy - (GLO + (cy - 1) * HV);
            const float fyh = (cy + 1 >= G - 1) ? 1e30f : (GLO + (cy + 2) * HV) - qy;
            const float fzl = (cz - 1 <= 0)     ? 1e30f : qz - (GLO + (cz - 1) * HV);
            const float fzh = (cz + 1 >= G - 1) ? 1e30f : (GLO + (cz + 2) * HV) - qz;
            const float lb  = fminf(fminf(fminf(fxl, fxh), fminf(fyl, fyh)),
                                    fminf(fzl, fzh));
            if (lb >= 1e29f) done = true;
            else if (j2 >= 0 && lb > 0.0f && m2 + MARGIN <= lb * lb) done = true;

            if (done) {
                const float e0 = sqrtf(fmaxf(m0, 1e-12f));
                const float e1 = sqrtf(fmaxf(m1, 1e-12f));
                const float e2 = sqrtf(fmaxf(m2, 1e-12f));
                const float r0 = __fdiv_rn(1.0f, __fadd_rn(e0, 1e-8f));
                const float r1 = __fdiv_rn(1.0f, __fadd_rn(e1, 1e-8f));
                const float r2 = __fdiv_rn(1.0f, __fadd_rn(e2, 1e-8f));
                const float s  = __fadd_rn(__fadd_rn(r0, r1), r2);
                const int bOut  = 3 * qid;
                g_idx[bOut + 0] = j0;
                g_idx[bOut + 1] = j1;
                g_idx[bOut + 2] = j2;
                g_w[bOut + 0]   = __fdiv_rn(r0, s);
                g_w[bOut + 1]   = __fdiv_rn(r1, s);
                g_w[bOut + 2]   = __fdiv_rn(r2, s);
            } else {
                g_far[atomicAdd(&g_nfar, 1)] = qbase + qi;
            }
        }
        __syncwarp();
    }
}

// ---------------------------------------------------------------------------
// knn_far: warp per unresolved query; mutually exclusive shells from rr=0.
// ---------------------------------------------------------------------------
#define FAR_T 256

__global__ void __launch_bounds__(FAR_T)
knn_far(int N, int M)
{
    const int nfar  = g_nfar;
    const int gwarp = (blockIdx.x * FAR_T + threadIdx.x) >> 5;
    const int lane  = threadIdx.x & 31;
    const int nwarp = (gridDim.x * FAR_T) >> 5;

    for (int i = gwarp; i < nfar; i += nwarp) {
        const int qslot = g_far[i];
        const int b     = qslot / M;
        const float4 Q  = g_qpts[qslot];
        const int   qid = g_qid[qslot];
        const float qx = Q.x, qy = Q.y, qz = Q.z, q2 = Q.w;
        const int cx = cell1(qx), cy = cell1(qy), cz = cell1(qz);
        const int bs = b * (G3 + 1), pbase = b * N;

        float d0 = 1e30f, d1 = 1e30f, d2v = 1e30f;
        int   i0 = -1,    i1 = -1,    i2 = -1;

        auto ins = [&](float dd, int id) {
            if (dd < d2v || (dd == d2v && id < i2)) {
                if (dd < d1 || (dd == d1 && id < i1)) {
                    d2v = d1; i2 = i1;
                    if (dd < d0 || (dd == d0 && id < i0)) {
                        d1 = d0; i1 = i0; d0 = dd; i0 = id;
                    } else { d1 = dd; i1 = id; }
                } else { d2v = dd; i2 = id; }
            }
        };
        auto dist2 = [&](const float4& P) -> float {
            const float cross = __fmaf_rn(qz, P.z,
                                  __fmaf_rn(qy, P.y, __fmul_rn(qx, P.x)));
            return __fmaf_rn(-2.0f, cross, __fadd_rn(q2, P.w));
        };
        auto scanrange = [&](int s, int e) {
            for (int p = s; p < e; p++) {
                const float4 P = g_pts[pbase + p];
                ins(dist2(P), g_pid[pbase + p]);
            }
        };

        float m0 = 1e30f, m1 = 1e30f, m2 = 1e30f;
        int   j0 = -1,    j1 = -1,    j2 = -1;
        auto insM = [&](float dd, int id) {
            if (dd < m2 || (dd == m2 && id < j2)) {
                if (dd < m1 || (dd == m1 && id < j1)) {
                    m2 = m1; j2 = j1;
                    if (dd < m0 || (dd == m0 && id < j0)) {
                        m1 = m0; j1 = j0; m0 = dd; j0 = id;
                    } else { m1 = dd; j1 = id; }
                } else { m2 = dd; j2 = id; }
            }
        };

        for (int rr = 0; ; rr++) {
            const int W = 2 * rr + 1;
            const int nrow = W * W;
            for (int t = lane; t < nrow; t += 32) {
                const int dz = t / W - rr, dy = t % W - rr;
                const int z = cz + dz, y = cy + dy;
                if (z < 0 || z >= G || y < 0 || y >= G) continue;
                const int row  = (z * G + y) * G;
                // EXCLUSIVE shell: boundary rows full x-span only.
                const bool full = (dz == -rr) || (dz == rr)
                               || (dy == -rr) || (dy == rr);
                if (full) {
                    const int xlo = max(cx - rr, 0), xhi = min(cx + rr, G - 1);
                    scanrange(__ldg(&g_start[bs + row + xlo]),
                              __ldg(&g_start[bs + row + xhi + 1]));
                } else {
                    if (cx - rr >= 0)
                        scanrange(__ldg(&g_start[bs + row + cx - rr]),
                                  __ldg(&g_start[bs + row + cx - rr + 1]));
                    if (cx + rr <= G - 1)
                        scanrange(__ldg(&g_start[bs + row + cx + rr]),
                                  __ldg(&g_start[bs + row + cx + rr + 1]));
                }
            }

            m0 = d0; m1 = d1; m2 = d2v; j0 = i0; j1 = i1; j2 = i2;
            for (int off = 16; off; off >>= 1) {
                const float b0 = __shfl_down_sync(0xFFFFFFFFu, m0, off);
                const float b1 = __shfl_down_sync(0xFFFFFFFFu, m1, off);
                const float b2 = __shfl_down_sync(0xFFFFFFFFu, m2, off);
                const int   c0 = __shfl_down_sync(0xFFFFFFFFu, j0, off);
                const int   c1 = __shfl_down_sync(0xFFFFFFFFu, j1, off);
                const int   c2 = __shfl_down_sync(0xFFFFFFFFu, j2, off);
                if (lane < off) { insM(b0, c0); insM(b1, c1); insM(b2, c2); }
            }
            const float m2b = __shfl_sync(0xFFFFFFFFu, m2, 0);
            const int   j2b = __shfl_sync(0xFFFFFFFFu, j2, 0);

            const float fxl = (cx - rr <= 0)     ? 1e30f : qx - (GLO + (cx - rr) * HV);
            const float fxh = (cx + rr >= G - 1) ? 1e30f : (GLO + (cx + rr + 1) * HV) - qx;
            const float fyl = (cy - rr <= 0)     ? 1e30f : qy - (GLO + (cy - rr) * HV);
            const float fyh = (cy + rr >= G - 1) ? 1e30f : (GLO + (cy + rr + 1) * HV) - qy;
            const float fzl = (cz - rr <= 0)     ? 1e30f : qz - (GLO + (cz - rr) * HV);
            const float fzh = (cz + rr >= G - 1) ? 1e30f : (GLO + (cz + rr + 1) * HV) - qz;
            const float lb  = fminf(fminf(fminf(fxl, fxh), fminf(fyl, fyh)),
                                    fminf(fzl, fzh));
            if (lb >= 1e29f) break;
            if (j2b >= 0 && lb > 0.0f && m2b + MARGIN <= lb * lb) break;
        }

        if (lane == 0) {
            const float e0 = sqrtf(fmaxf(m0, 1e-12f));
            const float e1 = sqrtf(fmaxf(m1, 1e-12f));
            const float e2 = sqrtf(fmaxf(m2, 1e-12f));
            const float r0 = __fdiv_rn(1.0f, __fadd_rn(e0, 1e-8f));
            const float r1 = __fdiv_rn(1.0f, __fadd_rn(e1, 1e-8f));
            const float r2 = __fdiv_rn(1.0f, __fadd_rn(e2, 1e-8f));
            const float s  = __fadd_rn(__fadd_rn(r0, r1), r2);
            const int bOut  = 3 * qid;          // ORIGINAL id (matches interp)
            g_idx[bOut + 0] = j0;
            g_idx[bOut + 1] = j1;
            g_idx[bOut + 2] = j2;
            g_w[bOut + 0]   = __fdiv_rn(r0, s);
            g_w[bOut + 1]   = __fdiv_rn(r1, s);
            g_w[bOut + 2]   = __fdiv_rn(r2, s);
        }
    }
}

__global__ void __launch_bounds__(256)
interp_kernel(const float* __restrict__ feat, float* __restrict__ out,
              int C4, int total)
{
    const int t = blockIdx.x * 256 + threadIdx.x;
    if (t >= total) return;

    const int q  = t / C4;
    const int cg = t - q * C4;

    const int   base = 3 * q;
    const int   i0 = g_idx[base + 0];
    const int   i1 = g_idx[base + 1];
    const int   i2 = g_idx[base + 2];
    const float w0 = g_w[base + 0];
    const float w1 = g_w[base + 1];
    const float w2 = g_w[base + 2];

    const float4* f = reinterpret_cast<const float4*>(feat);
    const float4 a = __ldg(f + (size_t)i0 * C4 + cg);
    const float4 b = __ldg(f + (size_t)i1 * C4 + cg);
    const float4 c = __ldg(f + (size_t)i2 * C4 + cg);

    float4 o;
    o.x = fmaf(w2, c.x, fmaf(w1, b.x, w0 * a.x));
    o.y = fmaf(w2, c.y, fmaf(w1, b.y, w0 * a.y));
    o.z = fmaf(w2, c.z, fmaf(w1, b.z, w0 * a.z));
    o.w = fmaf(w2, c.w, fmaf(w1, b.w, w0 * a.w));

    reinterpret_cast<float4*>(out)[t] = o;
}

extern "C" void kernel_launch(void* const* d_in, const int* in_sizes, int n_in,
                              void* d_out, int out_size)
{
    const float* xyz     = (const float*)d_in[0];
    const float* new_xyz = (const float*)d_in[1];
    const float* feat    = (const float*)d_in[2];

    const int B    = in_sizes[3];
    const int Ntot = in_sizes[0] / 3;
    const int Mtot = in_sizes[1] / 3;
    const int N    = Ntot / B;
    const int M    = Mtot / B;
    const int C    = in_sizes[2] / Ntot;

    const int cells = B * G3;
    const int tot   = Ntot + Mtot;

    // counters+g_nfar are zero on entry (static init first call, tail-zeroed)
    count_all<<<(tot + 255) / 256, 256>>>(xyz, new_xyz, N, Ntot, M, Mtot);   // 1
    scan_kernel<<<dim3(B, 2), 1024>>>();                                     // 2
    scatter_all<<<(tot + 255) / 256, 256>>>(xyz, new_xyz, N, Ntot, M, Mtot); // 3
    knn_cell<<<dim3(G3, B), KNN_T>>>(N, M);                                  // 4 <- profiled
    knn_far<<<256, FAR_T>>>(N, M);                                           // 5
    const int C4    = C / 4;
    const int total = Mtot * C4;
    interp_kernel<<<(total + 255) / 256, 256>>>(feat, (float*)d_out, C4, total); // 6
    zero_tail<<<(cells + 255) / 256, 256>>>(cells);                          // 7
}

// round 14
// speedup vs baseline: 1.4183x; 1.4183x over previous
#include <cuda_runtime.h>
#include <float.h>

// ---------------------------------------------------------------------------
// FeatPropagation via uniform-grid EXACT k=3 NN + inverse-distance interp.
//
// R14: MACRO-CELL dense phase. Evidence: R12 (thread-per-query, per-cell
// blocks) = cheap scan, 12% lane utilization; R13 (warp-per-query) = full
// lanes but 3x instructions (lost prefilter convergence + merge overhead).
// Fix: thread-per-query retained, but a block owns a 2x2x2 macro-cell and
// packs the UNION of its 8 cells' queries over 512 threads. Staged box =
// macro + 1-cell halo (4x4x4 cells, <=2048 cands, 40KB SMEM). Stop bound
// uses the staged-box faces (>= own-box bound) -> tiny far list.
//
// Ranking stays BIT-EXACT vs the JAX reference (GEMM-form d2 with explicit
// rounding intrinsics); (d2, index) lexicographic insert == top_k
// lowest-index tie-break, independent of partition/scatter/list order.
// ---------------------------------------------------------------------------

#define G      16
#define G3     (G * G * G)
#define GLO    (-4.0f)
#define HV     0.5f
#define INVH   2.0f
#define MAXB   8
#define MARGIN 2e-4f

__device__ int    g_cnt[MAXB * G3];
__device__ int    g_start[MAXB * (G3 + 1)];
__device__ int    g_cur[MAXB * G3];
__device__ float4 g_pts[1 << 15];
__device__ int    g_pid[1 << 15];
__device__ int    g_qcnt[MAXB * G3];
__device__ int    g_qstart[MAXB * (G3 + 1)];
__device__ int    g_qcur[MAXB * G3];
__device__ float4 g_qpts[1 << 17];
__device__ int    g_qid[1 << 17];
__device__ int    g_nfar;
__device__ int    g_far[1 << 17];

#define CAPQ (3 * (1 << 17))
__device__ int   g_idx[CAPQ];          // by ORIGINAL query id
__device__ float g_w[CAPQ];

__device__ __forceinline__ int cell1(float v) {
    int c = (int)floorf((v - GLO) * INVH);
    return min(max(c, 0), G - 1);
}

__global__ void count_all(const float* __restrict__ xyz,
                          const float* __restrict__ qxyz,
                          int N, int Ntot, int M, int Mtot) {
    int i = blockIdx.x * blockDim.x + threadIdx.x;
    if (i < Ntot) {
        int b = i / N;
        float x = xyz[3 * i], y = xyz[3 * i + 1], z = xyz[3 * i + 2];
        atomicAdd(g_cnt + b * G3 + (cell1(z) * G + cell1(y)) * G + cell1(x), 1);
    } else if (i < Ntot + Mtot) {
        int j = i - Ntot;
        int b = j / M;
        float x = qxyz[3 * j], y = qxyz[3 * j + 1], z = qxyz[3 * j + 2];
        atomicAdd(g_qcnt + b * G3 + (cell1(z) * G + cell1(y)) * G + cell1(x), 1);
    }
}

__global__ void __launch_bounds__(1024) scan_kernel() {
    const int b = blockIdx.x;
    int* cnt   = (blockIdx.y ? g_qcnt   : g_cnt)   + b * G3;
    int* start = (blockIdx.y ? g_qstart : g_start) + b * (G3 + 1);
    int* cur   = (blockIdx.y ? g_qcur   : g_cur)   + b * G3;

    const int tid = threadIdx.x;
    __shared__ int sm[1024];

    const int lo = tid * 4;
    int c0 = cnt[lo], c1 = cnt[lo + 1], c2 = cnt[lo + 2], c3 = cnt[lo + 3];
    const int sum = c0 + c1 + c2 + c3;
    sm[tid] = sum;
    __syncthreads();
    for (int off = 1; off < 1024; off <<= 1) {
        int v = (tid >= off) ? sm[tid - off] : 0;
        __syncthreads();
        sm[tid] += v;
        __syncthreads();
    }
    int run = sm[tid] - sum;
    start[lo]     = run;  cur[lo]     = run;  run += c0;
    start[lo + 1] = run;  cur[lo + 1] = run;  run += c1;
    start[lo + 2] = run;  cur[lo + 2] = run;  run += c2;
    start[lo + 3] = run;  cur[lo + 3] = run;
    if (tid == 1023) start[G3] = sm[1023];
}

__global__ void scatter_all(const float* __restrict__ xyz,
                            const float* __restrict__ qxyz,
                            int N, int Ntot, int M, int Mtot) {
    int i = blockIdx.x * blockDim.x + threadIdx.x;
    if (i < Ntot) {
        int b = i / N;
        float x = xyz[3 * i], y = xyz[3 * i + 1], z = xyz[3 * i + 2];
        int c = (cell1(z) * G + cell1(y)) * G + cell1(x);
        int pos = atomicAdd(g_cur + b * G3 + c, 1);
        float s2 = __fadd_rn(__fadd_rn(__fmul_rn(x, x), __fmul_rn(y, y)),
                             __fmul_rn(z, z));
        g_pts[b * N + pos] = make_float4(x, y, z, s2);
        g_pid[b * N + pos] = i;
    } else if (i < Ntot + Mtot) {
        int j = i - Ntot;
        int b = j / M;
        float x = qxyz[3 * j], y = qxyz[3 * j + 1], z = qxyz[3 * j + 2];
        int c = (cell1(z) * G + cell1(y)) * G + cell1(x);
        int pos = atomicAdd(g_qcur + b * G3 + c, 1);
        float s2 = __fadd_rn(__fadd_rn(__fmul_rn(x, x), __fmul_rn(y, y)),
                             __fmul_rn(z, z));
        g_qpts[b * M + pos] = make_float4(x, y, z, s2);
        g_qid [b * M + pos] = j;
    }
}

__global__ void zero_tail(int cells) {
    int i = blockIdx.x * blockDim.x + threadIdx.x;
    if (i < cells) { g_cnt[i] = 0; g_qcnt[i] = 0; }
    if (i == 0) g_nfar = 0;
}

// ---------------------------------------------------------------------------
// knn_macro: block per (2x2x2 macro-cell, batch). Stage the 4x4x4 halo box
// in SMEM; 512 threads, thread-per-query over the union of the 8 member
// cells' query ranges. Stop bound vs staged-box faces.
// ---------------------------------------------------------------------------
#define MG     (G / 2)                 // 8 macro cells per axis
#define MG3    (MG * MG * MG)          // 512
#define KNN_T  512
#define CAP_C  2048
#define MAXROW 16                      // (<=4 z) x (<=4 y) staged rows

__global__ void __launch_bounds__(KNN_T)
knn_macro(int N, int M)
{
    const int b  = blockIdx.y;
    const int mc = blockIdx.x;
    const int mz = mc / (MG * MG);
    const int my = (mc / MG) % MG;
    const int mx = mc % MG;

    const int bs    = b * (G3 + 1);
    const int pbase = b * N;
    const int qbase = b * M;
    const int tid   = threadIdx.x;

    // staged box (macro + halo), clamped
    const int Xlo = max(2 * mx - 1, 0), Xhi = min(2 * mx + 2, G - 1);
    const int Ylo = max(2 * my - 1, 0), Yhi = min(2 * my + 2, G - 1);
    const int Zlo = max(2 * mz - 1, 0), Zhi = min(2 * mz + 2, G - 1);
    const int Ysp = Yhi - Ylo + 1;
    const int nrows = (Zhi - Zlo + 1) * Ysp;

    __shared__ int    qsA[8], qoff[9];      // member-cell query ranges
    __shared__ int    rowS[MAXROW], rbase[MAXROW + 1];
    __shared__ float4 spts[CAP_C];
    __shared__ int    sid[CAP_C];

    if (tid < 8) {
        const int cz = 2 * mz + (tid >> 2);
        const int cy = 2 * my + ((tid >> 1) & 1);
        const int cx = 2 * mx + (tid & 1);
        const int c  = (cz * G + cy) * G + cx;
        qsA[tid]  = qbase + g_qstart[bs + c];
        qoff[tid] = g_qstart[bs + c + 1] - g_qstart[bs + c];  // count (temp)
    } else if (tid >= 32 && tid - 32 < nrows) {
        const int t = tid - 32;
        const int z = Zlo + t / Ysp;
        const int y = Ylo + t % Ysp;
        const int row = (z * G + y) * G;
        rowS[t]  = g_start[bs + row + Xlo];
        rbase[t] = g_start[bs + row + Xhi + 1] - rowS[t];     // len (temp)
    }
    __syncthreads();
    if (tid == 0) {                      // serial prefixes (tiny)
        int run = 0;
        for (int k = 0; k < 8; k++) { int v = qoff[k]; qoff[k] = run; run += v; }
        qoff[8] = run;
        run = 0;
        for (int r = 0; r < nrows; r++) { int v = rbase[r]; rbase[r] = run; run += v; }
        rbase[nrows] = run;
    }
    __syncthreads();

    const int Qtot  = qoff[8];
    if (Qtot == 0) return;
    const int total = rbase[nrows];

    if (total > CAP_C) {                 // safety punt (est. peak ~1400)
        for (int t = tid; t < Qtot; t += KNN_T) {
            int k = 0;
            #pragma unroll
            for (int u = 1; u < 8; u++) if (t >= qoff[u]) k = u;
            g_far[atomicAdd(&g_nfar, 1)] = qsA[k] + (t - qoff[k]);
        }
        return;
    }

    // cooperative fill: flatten rows, binary-search rbase
    for (int idx = tid; idx < total; idx += KNN_T) {
        int lo = 0, hi = nrows;
        while (hi - lo > 1) {            // <=4 steps
            const int mid = (lo + hi) >> 1;
            if (idx >= rbase[mid]) lo = mid; else hi = mid;
        }
        const int src = rowS[lo] + (idx - rbase[lo]);
        spts[idx] = g_pts[pbase + src];
        sid [idx] = g_pid[pbase + src];
    }
    __syncthreads();

    // staged-box face distances (covered grid edges -> +inf)
    const float FXL = (Xlo <= 0)     ? 1e30f : (GLO + Xlo * HV);
    const float FXH = (Xhi >= G - 1) ? 1e30f : (GLO + (Xhi + 1) * HV);
    const float FYL = (Ylo <= 0)     ? 1e30f : (GLO + Ylo * HV);
    const float FYH = (Yhi >= G - 1) ? 1e30f : (GLO + (Yhi + 1) * HV);
    const float FZL = (Zlo <= 0)     ? 1e30f : (GLO + Zlo * HV);
    const float FZH = (Zhi >= G - 1) ? 1e30f : (GLO + (Zhi + 1) * HV);

    // thread-per-query over the packed union of member-cell ranges
    for (int t = tid; t < Qtot; t += KNN_T) {
        int k = 0;
        #pragma unroll
        for (int u = 1; u < 8; u++) if (t >= qoff[u]) k = u;
        const int slot = qsA[k] + (t - qoff[k]);

        const float4 Q   = g_qpts[slot];
        const int    qid = g_qid[slot];
        const float qx = Q.x, qy = Q.y, qz = Q.z, q2 = Q.w;

        float d0 = 1e30f, d1 = 1e30f, d2v = 1e30f;
        int   i0 = -1,    i1 = -1,    i2 = -1;

        auto ins = [&](float dd, int id) {
            if (dd < d2v || (dd == d2v && id < i2)) {
                if (dd < d1 || (dd == d1 && id < i1)) {
                    d2v = d1; i2 = i1;
                    if (dd < d0 || (dd == d0 && id < i0)) {
                        d1 = d0; i1 = i0; d0 = dd; i0 = id;
                    } else { d1 = dd; i1 = id; }
                } else { d2v = dd; i2 = id; }
            }
        };
        auto dist2 = [&](const float4& P) -> float {
            const float cross = __fmaf_rn(qz, P.z,
                                  __fmaf_rn(qy, P.y, __fmul_rn(qx, P.x)));
            return __fmaf_rn(-2.0f, cross, __fadd_rn(q2, P.w));
        };

        // sequential scan (lockstep -> broadcast LDS), converged prefilter
        int j = 0;
        const int k4 = total & ~3;
        for (; j < k4; j += 4) {
            const float dd0 = dist2(spts[j]);
            const float dd1 = dist2(spts[j + 1]);
            const float dd2 = dist2(spts[j + 2]);
            const float dd3 = dist2(spts[j + 3]);
            const float gm  = fminf(fminf(dd0, dd1), fminf(dd2, dd3));
            if (gm <= d2v) {             // '<=' keeps tie-break exact
                ins(dd0, sid[j]);
                ins(dd1, sid[j + 1]);
                ins(dd2, sid[j + 2]);
                ins(dd3, sid[j + 3]);
            }
        }
        for (; j < total; j++)
            ins(dist2(spts[j]), sid[j]);

        // stop bound vs STAGED box faces
        const float lb = fminf(fminf(fminf(qx - FXL, FXH - qx),
                                     fminf(qy - FYL, FYH - qy)),
                               fminf(qz - FZL, FZH - qz));
        // note: covered faces give huge positive values (qx - (-1e30) etc.)
        const bool done = (i2 >= 0 && lb > 0.0f && d2v + MARGIN <= lb * lb);

        if (done) {
            const float e0 = sqrtf(fmaxf(d0,  1e-12f));
            const float e1 = sqrtf(fmaxf(d1,  1e-12f));
            const float e2 = sqrtf(fmaxf(d2v, 1e-12f));
            const float r0 = __fdiv_rn(1.0f, __fadd_rn(e0, 1e-8f));
            const float r1 = __fdiv_rn(1.0f, __fadd_rn(e1, 1e-8f));
            const float r2 = __fdiv_rn(1.0f, __fadd_rn(e2, 1e-8f));
            const float s  = __fadd_rn(__fadd_rn(r0, r1), r2);
            const int bO  = 3 * qid;
            g_idx[bO + 0] = i0;
            g_idx[bO + 1] = i1;
            g_idx[bO + 2] = i2;
            g_w[bO + 0]   = __fdiv_rn(r0, s);
            g_w[bO + 1]   = __fdiv_rn(r1, s);
            g_w[bO + 2]   = __fdiv_rn(r2, s);
        } else {
            g_far[atomicAdd(&g_nfar, 1)] = slot;
        }
    }
}

// ---------------------------------------------------------------------------
// knn_far: warp per unresolved query; mutually exclusive shells from rr=0.
// ---------------------------------------------------------------------------
#define FAR_T 256

__global__ void __launch_bounds__(FAR_T)
knn_far(int N, int M)
{
    const int nfar  = g_nfar;
    const int gwarp = (blockIdx.x * FAR_T + threadIdx.x) >> 5;
    const int lane  = threadIdx.x & 31;
    const int nwarp = (gridDim.x * FAR_T) >> 5;

    for (int i = gwarp; i < nfar; i += nwarp) {
        const int qslot = g_far[i];
        const int b     = qslot / M;
        const float4 Q  = g_qpts[qslot];
        const int   qid = g_qid[qslot];
        const float qx = Q.x, qy = Q.y, qz = Q.z, q2 = Q.w;
        const int cx = cell1(qx), cy = cell1(qy), cz = cell1(qz);
        const int bs = b * (G3 + 1), pbase = b * N;

        float d0 = 1e30f, d1 = 1e30f, d2v = 1e30f;
        int   i0 = -1,    i1 = -1,    i2 = -1;

        auto ins = [&](float dd, int id) {
            if (dd < d2v || (dd == d2v && id < i2)) {
                if (dd < d1 || (dd == d1 && id < i1)) {
                    d2v = d1; i2 = i1;
                    if (dd < d0 || (dd == d0 && id < i0)) {
                        d1 = d0; i1 = i0; d0 = dd; i0 = id;
                    } else { d1 = dd; i1 = id; }
                } else { d2v = dd; i2 = id; }
            }
        };
        auto dist2 = [&](const float4& P) -> float {
            const float cross = __fmaf_rn(qz, P.z,
                                  __fmaf_rn(qy, P.y, __fmul_rn(qx, P.x)));
            return __fmaf_rn(-2.0f, cross, __fadd_rn(q2, P.w));
        };
        auto scanrange = [&](int s, int e) {
            for (int p = s; p < e; p++) {
                const float4 P = g_pts[pbase + p];
                ins(dist2(P), g_pid[pbase + p]);
            }
        };

        float m0 = 1e30f, m1 = 1e30f, m2 = 1e30f;
        int   j0 = -1,    j1 = -1,    j2 = -1;
        auto insM = [&](float dd, int id) {
            if (dd < m2 || (dd == m2 && id < j2)) {
                if (dd < m1 || (dd == m1 && id < j1)) {
                    m2 = m1; j2 = j1;
                    if (dd < m0 || (dd == m0 && id < j0)) {
                        m1 = m0; j1 = j0; m0 = dd; j0 = id;
                    } else { m1 = dd; j1 = id; }
                } else { m2 = dd; j2 = id; }
            }
        };

        for (int rr = 0; ; rr++) {
            const int W = 2 * rr + 1;
            const int nrow = W * W;
            for (int t = lane; t < nrow; t += 32) {
                const int dz = t / W - rr, dy = t % W - rr;
                const int z = cz + dz, y = cy + dy;
                if (z < 0 || z >= G || y < 0 || y >= G) continue;
                const int row  = (z * G + y) * G;
                const bool full = (dz == -rr) || (dz == rr)
                               || (dy == -rr) || (dy == rr);
                if (full) {
                    const int xlo = max(cx - rr, 0), xhi = min(cx + rr, G - 1);
                    scanrange(__ldg(&g_start[bs + row + xlo]),
                              __ldg(&g_start[bs + row + xhi + 1]));
                } else {
                    if (cx - rr >= 0)
                        scanrange(__ldg(&g_start[bs + row + cx - rr]),
                                  __ldg(&g_start[bs + row + cx - rr + 1]));
                    if (cx + rr <= G - 1)
                        scanrange(__ldg(&g_start[bs + row + cx + rr]),
                                  __ldg(&g_start[bs + row + cx + rr + 1]));
                }
            }

            m0 = d0; m1 = d1; m2 = d2v; j0 = i0; j1 = i1; j2 = i2;
            for (int off = 16; off; off >>= 1) {
                const float b0 = __shfl_down_sync(0xFFFFFFFFu, m0, off);
                const float b1 = __shfl_down_sync(0xFFFFFFFFu, m1, off);
                const float b2 = __shfl_down_sync(0xFFFFFFFFu, m2, off);
                const int   c0 = __shfl_down_sync(0xFFFFFFFFu, j0, off);
                const int   c1 = __shfl_down_sync(0xFFFFFFFFu, j1, off);
                const int   c2 = __shfl_down_sync(0xFFFFFFFFu, j2, off);
                if (lane < off) { insM(b0, c0); insM(b1, c1); insM(b2, c2); }
            }
            const float m2b = __shfl_sync(0xFFFFFFFFu, m2, 0);
            const int   j2b = __shfl_sync(0xFFFFFFFFu, j2, 0);

            const float fxl = (cx - rr <= 0)     ? 1e30f : qx - (GLO + (cx - rr) * HV);
            const float fxh = (cx + rr >= G - 1) ? 1e30f : (GLO + (cx + rr + 1) * HV) - qx;
            const float fyl = (cy - rr <= 0)     ? 1e30f : qy - (GLO + (cy - rr) * HV);
            const float fyh = (cy + rr >= G - 1) ? 1e30f : (GLO + (cy + rr + 1) * HV) - qy;
            const float fzl = (cz - rr <= 0)     ? 1e30f : qz - (GLO + (cz - rr) * HV);
            const float fzh = (cz + rr >= G - 1) ? 1e30f : (GLO + (cz + rr + 1) * HV) - qz;
            const float lb  = fminf(fminf(fminf(fxl, fxh), fminf(fyl, fyh)),
                                    fminf(fzl, fzh));
            if (lb >= 1e29f) break;
            if (j2b >= 0 && lb > 0.0f && m2b + MARGIN <= lb * lb) break;
        }

        if (lane == 0) {
            const float e0 = sqrtf(fmaxf(m0, 1e-12f));
            const float e1 = sqrtf(fmaxf(m1, 1e-12f));
            const float e2 = sqrtf(fmaxf(m2, 1e-12f));
            const float r0 = __fdiv_rn(1.0f, __fadd_rn(e0, 1e-8f));
            const float r1 = __fdiv_rn(1.0f, __fadd_rn(e1, 1e-8f));
            const float r2 = __fdiv_rn(1.0f, __fadd_rn(e2, 1e-8f));
            const float s  = __fadd_rn(__fadd_rn(r0, r1), r2);
            const int bO  = 3 * qid;
            g_idx[bO + 0] = j0;
            g_idx[bO + 1] = j1;
            g_idx[bO + 2] = j2;
            g_w[bO + 0]   = __fdiv_rn(r0, s);
            g_w[bO + 1]   = __fdiv_rn(r1, s);
            g_w[bO + 2]   = __fdiv_rn(r2, s);
        }
    }
}

__global__ void __launch_bounds__(256)
interp_kernel(const float* __restrict__ feat, float* __restrict__ out,
              int C4, int total)
{
    const int t = blockIdx.x * 256 + threadIdx.x;
    if (t >= total) return;

    const int q  = t / C4;
    const int cg = t - q * C4;

    const int   base = 3 * q;
    const int   i0 = g_idx[base + 0];
    const int   i1 = g_idx[base + 1];
    const int   i2 = g_idx[base + 2];
    const float w0 = g_w[base + 0];
    const float w1 = g_w[base + 1];
    const float w2 = g_w[base + 2];

    const float4* f = reinterpret_cast<const float4*>(feat);
    const float4 a = __ldg(f + (size_t)i0 * C4 + cg);
    const float4 b = __ldg(f + (size_t)i1 * C4 + cg);
    const float4 c = __ldg(f + (size_t)i2 * C4 + cg);

    float4 o;
    o.x = fmaf(w2, c.x, fmaf(w1, b.x, w0 * a.x));
    o.y = fmaf(w2, c.y, fmaf(w1, b.y, w0 * a.y));
    o.z = fmaf(w2, c.z, fmaf(w1, b.z, w0 * a.z));
    o.w = fmaf(w2, c.w, fmaf(w1, b.w, w0 * a.w));

    reinterpret_cast<float4*>(out)[t] = o;
}

extern "C" void kernel_launch(void* const* d_in, const int* in_sizes, int n_in,
                              void* d_out, int out_size)
{
    const float* xyz     = (const float*)d_in[0];
    const float* new_xyz = (const float*)d_in[1];
    const float* feat    = (const float*)d_in[2];

    const int B    = in_sizes[3];
    const int Ntot = in_sizes[0] / 3;
    const int Mtot = in_sizes[1] / 3;
    const int N    = Ntot / B;
    const int M    = Mtot / B;
    const int C    = in_sizes[2] / Ntot;

    const int cells = B * G3;
    const int tot   = Ntot + Mtot;

    count_all<<<(tot + 255) / 256, 256>>>(xyz, new_xyz, N, Ntot, M, Mtot);   // 1
    scan_kernel<<<dim3(B, 2), 1024>>>();                                     // 2
    scatter_all<<<(tot + 255) / 256, 256>>>(xyz, new_xyz, N, Ntot, M, Mtot); // 3
    knn_macro<<<dim3(MG3, B), KNN_T>>>(N, M);                                // 4 <- profiled
    knn_far<<<256, FAR_T>>>(N, M);                                           // 5
    const int C4    = C / 4;
    const int total = Mtot * C4;
    interp_kernel<<<(total + 255) / 256, 256>>>(feat, (float*)d_out, C4, total); // 6
    zero_tail<<<(cells + 255) / 256, 256>>>(cells);                          // 7
}